// round 13
// baseline (speedup 1.0000x reference)
#include <cuda_runtime.h>
#include <cuda_fp16.h>
#include <cstdint>

// 3x3 conv s1 p1, implicit GEMM via mma.sync m16n8k16 fp16 (f32 accum).
// R13: CTA tile 128m x 256n (full cout) -> per-SM LDSM bytes and producer
// global traffic halve at constant MMA work. 8 warps of 64x64 tiles, 1 CTA/SM.
// K-chunk 64, NHWC prepass, ldmatrix.x4, 3-stage B / 2-stage A, A tile
// shared across 3 kw chunks via +144B row shift.

#define HH 512
#define WW 512
#define HWSZ (512*512)
#define NCHUNK 36
#define RPITCH 36                            // u32 per row (32 used + 4 pad), 144B
#define ATILE_BYTES (132 * RPITCH * 4)       // 19008
#define BTILE_BYTES (256 * RPITCH * 4)       // 36864
#define A_OFF 0
#define B_OFF (2 * ATILE_BYTES)              // 38016
#define SMEM_BYTES (2 * ATILE_BYTES + 3 * BTILE_BYTES)   // 148608
#define NTHREADS 256

// scratch (bss, not allocations)
__device__ uint32_t g_x2[HWSZ * 128];            // NHWC: [pixel][cipair] half2
__device__ uint32_t g_w[9 * 4 * 256 * 32];       // [k9][cic2][n256][kp32] half2

__device__ __forceinline__ uint32_t packh2(float lo, float hi) {
    uint32_t d;
    asm("cvt.rn.f16x2.f32 %0, %1, %2;" : "=r"(d) : "f"(hi), "f"(lo));
    return d;
}
__device__ __forceinline__ void cp_async16(uint32_t dst, const void* src) {
    asm volatile("cp.async.cg.shared.global [%0], [%1], 16;"
                 :: "r"(dst), "l"(src) : "memory");
}
__device__ __forceinline__ void cp_async16z(uint32_t dst, const void* src, uint32_t sz) {
    asm volatile("cp.async.cg.shared.global [%0], [%1], 16, %2;"
                 :: "r"(dst), "l"(src), "r"(sz) : "memory");
}
__device__ __forceinline__ void cp_commit() {
    asm volatile("cp.async.commit_group;" ::: "memory");
}
__device__ __forceinline__ void cp_wait1() {
    asm volatile("cp.async.wait_group 1;" ::: "memory");
}
__device__ __forceinline__ void ldsm4(uint32_t* r, uint32_t addr) {
    asm volatile("ldmatrix.sync.aligned.m8n8.x4.shared.b16 {%0,%1,%2,%3}, [%4];"
                 : "=r"(r[0]), "=r"(r[1]), "=r"(r[2]), "=r"(r[3]) : "r"(addr));
}
__device__ __forceinline__ void mma_fp16(float* c, const uint32_t* a, const uint32_t* b) {
    asm volatile(
        "mma.sync.aligned.m16n8k16.row.col.f32.f16.f16.f32 "
        "{%0,%1,%2,%3}, {%4,%5,%6,%7}, {%8,%9}, {%0,%1,%2,%3};"
        : "+f"(c[0]), "+f"(c[1]), "+f"(c[2]), "+f"(c[3])
        : "r"(a[0]), "r"(a[1]), "r"(a[2]), "r"(a[3]), "r"(b[0]), "r"(b[1]));
}

// ---------------- prepasses ----------------
__global__ void prep_x(const float* __restrict__ x) {
    const int t = blockIdx.x * 256 + threadIdx.x;   // HWSZ*4 threads
    const int p = t >> 2;
    const int j = t & 3;
#pragma unroll
    for (int i = 0; i < 8; i++) {
        const int cp0 = 4 * j + 16 * i;
        uint32_t o[4];
#pragma unroll
        for (int e = 0; e < 4; e++) {
            const int cp = cp0 + e;
            const float lo = x[(size_t)(2 * cp) * HWSZ + p];
            const float hi = x[(size_t)(2 * cp + 1) * HWSZ + p];
            o[e] = packh2(lo, hi);
        }
        *reinterpret_cast<uint4*>(g_x2 + (size_t)p * 128 + cp0) =
            make_uint4(o[0], o[1], o[2], o[3]);
    }
}
__global__ void prep_w(const float* __restrict__ w) {
    const int t = blockIdx.x * 256 + threadIdx.x;   // 294912
    const int kp   = t & 31;
    const int n    = (t >> 5) & 255;
    const int cic2 = (t >> 13) & 3;
    const int k9   = t >> 15;
    const int ci = cic2 * 64 + kp * 2;
    const float lo = w[((size_t)k9 * 256 + ci) * 256 + n];
    const float hi = w[((size_t)k9 * 256 + ci + 1) * 256 + n];
    g_w[(((size_t)k9 * 4 + cic2) * 256 + n) * 32 + kp] = packh2(lo, hi);
}

// ---------------- main kernel ----------------
__global__ void __launch_bounds__(NTHREADS, 1)
conv_mma(const float* __restrict__ bias, float* __restrict__ out)
{
    extern __shared__ uint32_t dsm[];

    const int tid  = threadIdx.x;
    const int wid  = tid >> 5;
    const int lane = tid & 31;
    const int gid  = lane >> 2;
    const int tig  = lane & 3;
    const int wm   = wid & 1;      // warp m-offset: 64*wm
    const int wn   = wid >> 1;     // warp n-offset: 64*wn (0..3)

    const int w0 = blockIdx.x * 128;
    const int h  = blockIdx.y;

    const uint32_t sbase = (uint32_t)__cvta_generic_to_shared(dsm);

    float acc[4][8][4];
#pragma unroll
    for (int mt = 0; mt < 4; mt++)
#pragma unroll
        for (int nt = 0; nt < 8; nt++)
#pragma unroll
            for (int i = 0; i < 4; i++)
                acc[mt][nt][i] = 0.f;

    // A tile for at = kh*4 + cic2: 132 rows (pixels w0-1..w0+130),
    // 32 u32 of k per row, pitch 36 u32. 2 stages.
    auto load_A = [&](int at, int stage) {
        const int kh   = at >> 2;
        const int cic2 = at & 3;
        const uint32_t abase = sbase + A_OFF + (uint32_t)stage * ATILE_BYTES;

        const int h2 = h + kh - 1;
        const bool hok = (unsigned)h2 < (unsigned)HH;
        const int rowbase = (hok ? h2 : 0) * WW;

#pragma unroll
        for (int i = 0; i < 5; i++) {              // 1056 tasks
            const int j = tid + i * NTHREADS;
            if (j < 1056) {
                const int pix = j >> 3, q = j & 7;
                const int w2 = w0 + pix - 1;
                const bool ok = hok && ((unsigned)w2 < (unsigned)WW);
                const uint32_t* src =
                    g_x2 + ((size_t)(rowbase + (ok ? w2 : 0)) * 128 + cic2 * 32 + q * 4);
                cp_async16z(abase + (uint32_t)(pix * RPITCH + q * 4) * 4u,
                            src, ok ? 16u : 0u);
            }
        }
    };
    // B tile for chunk c (kh, cic2, kw innermost): 256 rows x 32 u32. 3 stages.
    auto load_B = [&](int c, int stage) {
        const int kh   = c / 12;
        const int r    = c % 12;
        const int cic2 = r / 3;
        const int kw   = r % 3;
        const uint32_t bbase = sbase + B_OFF + (uint32_t)stage * BTILE_BYTES;
        const uint32_t* wb =
            g_w + ((size_t)((kh * 3 + kw) * 4 + cic2)) * 8192;
#pragma unroll
        for (int i = 0; i < 8; i++) {
            const int j = tid + i * NTHREADS;      // 2048 tasks
            const int n = j >> 3, q = j & 7;
            cp_async16(bbase + (uint32_t)(n * RPITCH + q * 4) * 4u, wb + j * 4);
        }
    };

    load_A(0, 0); load_B(0, 0); cp_commit();
    load_B(1, 1); cp_commit();

    // per-lane ldmatrix base offsets (bytes); pitch 144B
    const uint32_t laneA = (uint32_t)((wm * 64 + (lane & 15)) * 144 + ((lane >> 4) << 4));
    const uint32_t laneB = (uint32_t)((wn * 64 + ((lane >> 4) << 3) + (lane & 7)) * 144 +
                                      (((lane >> 3) & 1) << 4));

    for (int c = 0; c < NCHUNK; c++) {
        cp_wait1();
        __syncthreads();

        const int kw = c % 3;
        const uint32_t sA = sbase + A_OFF +
                            (uint32_t)(((c / 3) & 1) ? ATILE_BYTES : 0) +
                            (uint32_t)(kw * 144);           // kw row shift
        const uint32_t sB = sbase + B_OFF + (uint32_t)((c % 3) * BTILE_BYTES);

#pragma unroll
        for (int ks = 0; ks < 4; ks++) {
            uint32_t afrag[4][4];
#pragma unroll
            for (int mt = 0; mt < 4; mt++)
                ldsm4(afrag[mt], sA + laneA + (uint32_t)(mt * 16 * 144 + ks * 32));
            uint32_t bfrag[8][2];
#pragma unroll
            for (int np = 0; np < 4; np++) {
                uint32_t r[4];
                ldsm4(r, sB + laneB + (uint32_t)(np * 16 * 144 + ks * 32));
                bfrag[2 * np][0]     = r[0];
                bfrag[2 * np][1]     = r[1];
                bfrag[2 * np + 1][0] = r[2];
                bfrag[2 * np + 1][1] = r[3];
            }
#pragma unroll
            for (int mt = 0; mt < 4; mt++)
#pragma unroll
                for (int nt = 0; nt < 8; nt++)
                    mma_fp16(acc[mt][nt], afrag[mt], bfrag[nt]);
        }

        // no trailing __syncthreads: B 3-staged ((c+2)%3 != c%3); A prefetch
        // (only when (c+2)%3==0) targets the opposite A parity.
        const int cn = c + 2;
        if (cn < NCHUNK) {
            if (cn % 3 == 0) load_A(cn / 3, (cn / 3) & 1);
            load_B(cn, cn % 3);
        }
        cp_commit();
    }

    // ---- epilogue: bias + store ----
    const size_t prow = (size_t)h * WW + w0;
#pragma unroll
    for (int nt = 0; nt < 8; nt++) {
        const int co = wn * 64 + nt * 8 + tig * 2;
        const float b0 = __ldg(bias + co);
        const float b1 = __ldg(bias + co + 1);
        float* o0 = out + (size_t)co * HWSZ + prow;
        float* o1 = o0 + HWSZ;
#pragma unroll
        for (int mt = 0; mt < 4; mt++) {
            const int m = wm * 64 + mt * 16 + gid;
            o0[m]     = acc[mt][nt][0] + b0;
            o1[m]     = acc[mt][nt][1] + b1;
            o0[m + 8] = acc[mt][nt][2] + b0;
            o1[m + 8] = acc[mt][nt][3] + b1;
        }
    }
}

extern "C" void kernel_launch(void* const* d_in, const int* in_sizes, int n_in,
                              void* d_out, int out_size) {
    const float* x = (const float*)d_in[0];   // [256,512,512]
    const float* w = (const float*)d_in[1];   // [3,3,256,256]
    const float* b = (const float*)d_in[2];   // [256]
    float* out = (float*)d_out;               // [256,512,512]

    prep_x<<<(HWSZ * 4) / 256, 256>>>(x);
    prep_w<<<(9 * 4 * 256 * 32) / 256, 256>>>(w);

    cudaFuncSetAttribute(conv_mma, cudaFuncAttributeMaxDynamicSharedMemorySize, SMEM_BYTES);
    dim3 grid(4, HH, 1);   // 4 w-tiles x 512 rows, full cout per CTA
    conv_mma<<<grid, NTHREADS, SMEM_BYTES>>>(b, out);
}

// round 14
// speedup vs baseline: 1.0375x; 1.0375x over previous
#include <cuda_runtime.h>
#include <cuda_fp16.h>
#include <cstdint>

// 3x3 conv s1 p1, implicit GEMM via mma.sync m16n8k16 fp16 (f32 accum).
// R14 = R11 base (4 warps x 64x64, K-chunk 64, 2 CTAs/SM) +
//  (a) ks-loop fragment double-buffering (LDSM for ks+1 overlaps MMAs for ks)
//  (b) producers issued right after the barrier, before the MMA block.
// NHWC prepass, ldmatrix.x4, 3-stage B / 2-stage A, A tile shared across
// 3 kw chunks via +144B row shift.

#define HH 512
#define WW 512
#define HWSZ (512*512)
#define NCHUNK 36
#define RPITCH 36                            // u32 per row (32 used + 4 pad), 144B
#define ATILE_BYTES (132 * RPITCH * 4)       // 19008
#define BTILE_BYTES (128 * RPITCH * 4)       // 18432
#define A_OFF 0
#define B_OFF (2 * ATILE_BYTES)              // 38016
#define SMEM_BYTES (2 * ATILE_BYTES + 3 * BTILE_BYTES)   // 93312
#define NTHREADS 128

// scratch (bss, not allocations)
__device__ uint32_t g_x2[HWSZ * 128];            // NHWC: [pixel][cipair] half2
__device__ uint32_t g_w[9 * 4 * 2 * 128 * 32];   // [k9][cic2][coh][n][kp32] half2

__device__ __forceinline__ uint32_t packh2(float lo, float hi) {
    uint32_t d;
    asm("cvt.rn.f16x2.f32 %0, %1, %2;" : "=r"(d) : "f"(hi), "f"(lo));
    return d;
}
__device__ __forceinline__ void cp_async16(uint32_t dst, const void* src) {
    asm volatile("cp.async.cg.shared.global [%0], [%1], 16;"
                 :: "r"(dst), "l"(src) : "memory");
}
__device__ __forceinline__ void cp_async16z(uint32_t dst, const void* src, uint32_t sz) {
    asm volatile("cp.async.cg.shared.global [%0], [%1], 16, %2;"
                 :: "r"(dst), "l"(src), "r"(sz) : "memory");
}
__device__ __forceinline__ void cp_commit() {
    asm volatile("cp.async.commit_group;" ::: "memory");
}
__device__ __forceinline__ void cp_wait1() {
    asm volatile("cp.async.wait_group 1;" ::: "memory");
}
__device__ __forceinline__ void ldsm4(uint32_t* r, uint32_t addr) {
    asm volatile("ldmatrix.sync.aligned.m8n8.x4.shared.b16 {%0,%1,%2,%3}, [%4];"
                 : "=r"(r[0]), "=r"(r[1]), "=r"(r[2]), "=r"(r[3]) : "r"(addr));
}
__device__ __forceinline__ void mma_fp16(float* c, const uint32_t* a, const uint32_t* b) {
    asm volatile(
        "mma.sync.aligned.m16n8k16.row.col.f32.f16.f16.f32 "
        "{%0,%1,%2,%3}, {%4,%5,%6,%7}, {%8,%9}, {%0,%1,%2,%3};"
        : "+f"(c[0]), "+f"(c[1]), "+f"(c[2]), "+f"(c[3])
        : "r"(a[0]), "r"(a[1]), "r"(a[2]), "r"(a[3]), "r"(b[0]), "r"(b[1]));
}

// ---------------- prepasses ----------------
__global__ void prep_x(const float* __restrict__ x) {
    const int t = blockIdx.x * 256 + threadIdx.x;   // HWSZ*4 threads
    const int p = t >> 2;
    const int j = t & 3;
#pragma unroll
    for (int i = 0; i < 8; i++) {
        const int cp0 = 4 * j + 16 * i;
        uint32_t o[4];
#pragma unroll
        for (int e = 0; e < 4; e++) {
            const int cp = cp0 + e;
            const float lo = x[(size_t)(2 * cp) * HWSZ + p];
            const float hi = x[(size_t)(2 * cp + 1) * HWSZ + p];
            o[e] = packh2(lo, hi);
        }
        *reinterpret_cast<uint4*>(g_x2 + (size_t)p * 128 + cp0) =
            make_uint4(o[0], o[1], o[2], o[3]);
    }
}
__global__ void prep_w(const float* __restrict__ w) {
    const int t = blockIdx.x * 256 + threadIdx.x;   // 294912
    const int kp   = t & 31;
    const int n    = (t >> 5) & 127;
    const int coh  = (t >> 12) & 1;
    const int cic2 = (t >> 13) & 3;
    const int k9   = t >> 15;
    const int ci = cic2 * 64 + kp * 2;
    const int co = coh * 128 + n;
    const float lo = w[((size_t)k9 * 256 + ci) * 256 + co];
    const float hi = w[((size_t)k9 * 256 + ci + 1) * 256 + co];
    g_w[((((size_t)k9 * 4 + cic2) * 2 + coh) * 128 + n) * 32 + kp] = packh2(lo, hi);
}

// ---------------- main kernel ----------------
__global__ void __launch_bounds__(NTHREADS, 2)
conv_mma(const float* __restrict__ bias, float* __restrict__ out)
{
    extern __shared__ uint32_t dsm[];

    const int tid  = threadIdx.x;
    const int wid  = tid >> 5;
    const int lane = tid & 31;
    const int gid  = lane >> 2;
    const int tig  = lane & 3;
    const int wm   = wid & 1;      // warp m-offset: 64*wm
    const int wn   = wid >> 1;     // warp n-offset: 64*wn

    const int w0  = blockIdx.x * 128;
    const int h   = blockIdx.y;
    const int coh = blockIdx.z;
    const int co0 = coh * 128;

    const uint32_t sbase = (uint32_t)__cvta_generic_to_shared(dsm);

    float acc[4][8][4];
#pragma unroll
    for (int mt = 0; mt < 4; mt++)
#pragma unroll
        for (int nt = 0; nt < 8; nt++)
#pragma unroll
            for (int i = 0; i < 4; i++)
                acc[mt][nt][i] = 0.f;

    // A tile for at = kh*4 + cic2: 132 rows (pixels w0-1..w0+130),
    // 32 u32 of k per row, pitch 36 u32. 2 stages.
    auto load_A = [&](int at, int stage) {
        const int kh   = at >> 2;
        const int cic2 = at & 3;
        const uint32_t abase = sbase + A_OFF + (uint32_t)stage * ATILE_BYTES;

        const int h2 = h + kh - 1;
        const bool hok = (unsigned)h2 < (unsigned)HH;
        const int rowbase = (hok ? h2 : 0) * WW;

#pragma unroll
        for (int i = 0; i < 9; i++) {              // 1056 tasks
            const int j = tid + i * NTHREADS;
            if (j < 1056) {
                const int pix = j >> 3, q = j & 7;
                const int w2 = w0 + pix - 1;
                const bool ok = hok && ((unsigned)w2 < (unsigned)WW);
                const uint32_t* src =
                    g_x2 + ((size_t)(rowbase + (ok ? w2 : 0)) * 128 + cic2 * 32 + q * 4);
                cp_async16z(abase + (uint32_t)(pix * RPITCH + q * 4) * 4u,
                            src, ok ? 16u : 0u);
            }
        }
    };
    // B tile for chunk c (kh, cic2, kw innermost): 128 rows x 32 u32. 3 stages.
    auto load_B = [&](int c, int stage) {
        const int kh   = c / 12;
        const int r    = c % 12;
        const int cic2 = r / 3;
        const int kw   = r % 3;
        const uint32_t bbase = sbase + B_OFF + (uint32_t)stage * BTILE_BYTES;
        const uint32_t* wb =
            g_w + (((size_t)(kh * 3 + kw) * 4 + cic2) * 2 + coh) * 4096;
#pragma unroll
        for (int i = 0; i < 8; i++) {
            const int j = tid + i * NTHREADS;      // 1024 tasks
            const int n = j >> 3, q = j & 7;
            cp_async16(bbase + (uint32_t)(n * RPITCH + q * 4) * 4u, wb + j * 4);
        }
    };

    load_A(0, 0); load_B(0, 0); cp_commit();
    load_B(1, 1); cp_commit();

    // per-lane ldmatrix base offsets (bytes); pitch 144B
    const uint32_t laneA = (uint32_t)((wm * 64 + (lane & 15)) * 144 + ((lane >> 4) << 4));
    const uint32_t laneB = (uint32_t)((wn * 64 + ((lane >> 4) << 3) + (lane & 7)) * 144 +
                                      (((lane >> 3) & 1) << 4));

    for (int c = 0; c < NCHUNK; c++) {
        cp_wait1();
        __syncthreads();

        // producers first: stage (c+2)%3 == (c-1)%3, whose readers finished
        // before the barrier above; DMA overlaps this iteration's MMAs.
        const int cn = c + 2;
        if (cn < NCHUNK) {
            if (cn % 3 == 0) load_A(cn / 3, (cn / 3) & 1);
            load_B(cn, cn % 3);
        }
        cp_commit();

        const int kw = c % 3;
        const uint32_t sA = sbase + A_OFF +
                            (uint32_t)(((c / 3) & 1) ? ATILE_BYTES : 0) +
                            (uint32_t)(kw * 144);           // kw row shift
        const uint32_t sB = sbase + B_OFF + (uint32_t)((c % 3) * BTILE_BYTES);

        // fragment double-buffering across ks
        uint32_t afrag[2][4][4];
        uint32_t bfrag[2][8][2];

        auto load_frags = [&](int ks, int buf) {
#pragma unroll
            for (int mt = 0; mt < 4; mt++)
                ldsm4(afrag[buf][mt], sA + laneA + (uint32_t)(mt * 16 * 144 + ks * 32));
#pragma unroll
            for (int np = 0; np < 4; np++) {
                uint32_t r[4];
                ldsm4(r, sB + laneB + (uint32_t)(np * 16 * 144 + ks * 32));
                bfrag[buf][2 * np][0]     = r[0];
                bfrag[buf][2 * np][1]     = r[1];
                bfrag[buf][2 * np + 1][0] = r[2];
                bfrag[buf][2 * np + 1][1] = r[3];
            }
        };

        load_frags(0, 0);
#pragma unroll
        for (int ks = 0; ks < 4; ks++) {
            const int cur = ks & 1;
            if (ks < 3) load_frags(ks + 1, cur ^ 1);
#pragma unroll
            for (int mt = 0; mt < 4; mt++)
#pragma unroll
                for (int nt = 0; nt < 8; nt++)
                    mma_fp16(acc[mt][nt], afrag[cur][mt], bfrag[cur][nt]);
        }
        // no trailing __syncthreads (3-stage B / 2-stage A safety as before)
    }

    // ---- epilogue: bias + store ----
    const size_t prow = (size_t)h * WW + w0;
#pragma unroll
    for (int nt = 0; nt < 8; nt++) {
        const int co = co0 + wn * 64 + nt * 8 + tig * 2;
        const float b0 = __ldg(bias + co);
        const float b1 = __ldg(bias + co + 1);
        float* o0 = out + (size_t)co * HWSZ + prow;
        float* o1 = o0 + HWSZ;
#pragma unroll
        for (int mt = 0; mt < 4; mt++) {
            const int m = wm * 64 + mt * 16 + gid;
            o0[m]     = acc[mt][nt][0] + b0;
            o1[m]     = acc[mt][nt][1] + b1;
            o0[m + 8] = acc[mt][nt][2] + b0;
            o1[m + 8] = acc[mt][nt][3] + b1;
        }
    }
}

extern "C" void kernel_launch(void* const* d_in, const int* in_sizes, int n_in,
                              void* d_out, int out_size) {
    const float* x = (const float*)d_in[0];   // [256,512,512]
    const float* w = (const float*)d_in[1];   // [3,3,256,256]
    const float* b = (const float*)d_in[2];   // [256]
    float* out = (float*)d_out;               // [256,512,512]

    prep_x<<<(HWSZ * 4) / 256, 256>>>(x);
    prep_w<<<(9 * 4 * 2 * 128 * 32) / 256, 256>>>(w);

    cudaFuncSetAttribute(conv_mma, cudaFuncAttributeMaxDynamicSharedMemorySize, SMEM_BYTES);
    dim3 grid(4, HH, 2);   // 4 w-tiles x 512 rows x 2 cout halves
    conv_mma<<<grid, NTHREADS, SMEM_BYTES>>>(b, out);
}

// round 15
// speedup vs baseline: 1.0951x; 1.0555x over previous
#include <cuda_runtime.h>
#include <cuda_fp16.h>
#include <cstdint>

// 3x3 conv s1 p1, implicit GEMM via mma.sync m16n8k16 fp16 (f32 accum).
// R15 = R11 (best: 769.6us) + bias staged via smem + streaming epilogue stores.
// 4 warps x 64x64 warp tiles, K-chunk 64, 2 CTAs/SM, NHWC prepass,
// ldmatrix.x4, 3-stage B / 2-stage A, A tile shared across 3 kw chunks
// via +144B row shift, no trailing barrier.

#define HH 512
#define WW 512
#define HWSZ (512*512)
#define NCHUNK 36
#define RPITCH 36                            // u32 per row (32 used + 4 pad), 144B
#define ATILE_BYTES (132 * RPITCH * 4)       // 19008
#define BTILE_BYTES (128 * RPITCH * 4)       // 18432
#define A_OFF 0
#define B_OFF (2 * ATILE_BYTES)              // 38016
#define SMEM_BYTES (2 * ATILE_BYTES + 3 * BTILE_BYTES)   // 93312
#define NTHREADS 128

// scratch (bss, not allocations)
__device__ uint32_t g_x2[HWSZ * 128];            // NHWC: [pixel][cipair] half2
__device__ uint32_t g_w[9 * 4 * 2 * 128 * 32];   // [k9][cic2][coh][n][kp32] half2

__device__ __forceinline__ uint32_t packh2(float lo, float hi) {
    uint32_t d;
    asm("cvt.rn.f16x2.f32 %0, %1, %2;" : "=r"(d) : "f"(hi), "f"(lo));
    return d;
}
__device__ __forceinline__ void cp_async16(uint32_t dst, const void* src) {
    asm volatile("cp.async.cg.shared.global [%0], [%1], 16;"
                 :: "r"(dst), "l"(src) : "memory");
}
__device__ __forceinline__ void cp_async16z(uint32_t dst, const void* src, uint32_t sz) {
    asm volatile("cp.async.cg.shared.global [%0], [%1], 16, %2;"
                 :: "r"(dst), "l"(src), "r"(sz) : "memory");
}
__device__ __forceinline__ void cp_commit() {
    asm volatile("cp.async.commit_group;" ::: "memory");
}
__device__ __forceinline__ void cp_wait1() {
    asm volatile("cp.async.wait_group 1;" ::: "memory");
}
__device__ __forceinline__ void ldsm4(uint32_t* r, uint32_t addr) {
    asm volatile("ldmatrix.sync.aligned.m8n8.x4.shared.b16 {%0,%1,%2,%3}, [%4];"
                 : "=r"(r[0]), "=r"(r[1]), "=r"(r[2]), "=r"(r[3]) : "r"(addr));
}
__device__ __forceinline__ void mma_fp16(float* c, const uint32_t* a, const uint32_t* b) {
    asm volatile(
        "mma.sync.aligned.m16n8k16.row.col.f32.f16.f16.f32 "
        "{%0,%1,%2,%3}, {%4,%5,%6,%7}, {%8,%9}, {%0,%1,%2,%3};"
        : "+f"(c[0]), "+f"(c[1]), "+f"(c[2]), "+f"(c[3])
        : "r"(a[0]), "r"(a[1]), "r"(a[2]), "r"(a[3]), "r"(b[0]), "r"(b[1]));
}
__device__ __forceinline__ void stcg(float* p, float v) {
    asm volatile("st.global.cg.f32 [%0], %1;" :: "l"(p), "f"(v) : "memory");
}

// ---------------- prepasses ----------------
__global__ void prep_x(const float* __restrict__ x) {
    const int t = blockIdx.x * 256 + threadIdx.x;   // HWSZ*4 threads
    const int p = t >> 2;
    const int j = t & 3;
#pragma unroll
    for (int i = 0; i < 8; i++) {
        const int cp0 = 4 * j + 16 * i;
        uint32_t o[4];
#pragma unroll
        for (int e = 0; e < 4; e++) {
            const int cp = cp0 + e;
            const float lo = x[(size_t)(2 * cp) * HWSZ + p];
            const float hi = x[(size_t)(2 * cp + 1) * HWSZ + p];
            o[e] = packh2(lo, hi);
        }
        *reinterpret_cast<uint4*>(g_x2 + (size_t)p * 128 + cp0) =
            make_uint4(o[0], o[1], o[2], o[3]);
    }
}
__global__ void prep_w(const float* __restrict__ w) {
    const int t = blockIdx.x * 256 + threadIdx.x;   // 294912
    const int kp   = t & 31;
    const int n    = (t >> 5) & 127;
    const int coh  = (t >> 12) & 1;
    const int cic2 = (t >> 13) & 3;
    const int k9   = t >> 15;
    const int ci = cic2 * 64 + kp * 2;
    const int co = coh * 128 + n;
    const float lo = w[((size_t)k9 * 256 + ci) * 256 + co];
    const float hi = w[((size_t)k9 * 256 + ci + 1) * 256 + co];
    g_w[((((size_t)k9 * 4 + cic2) * 2 + coh) * 128 + n) * 32 + kp] = packh2(lo, hi);
}

// ---------------- main kernel ----------------
__global__ void __launch_bounds__(NTHREADS, 2)
conv_mma(const float* __restrict__ bias, float* __restrict__ out)
{
    extern __shared__ uint32_t dsm[];
    __shared__ float s_bias[128];

    const int tid  = threadIdx.x;
    const int wid  = tid >> 5;
    const int lane = tid & 31;
    const int gid  = lane >> 2;
    const int tig  = lane & 3;
    const int wm   = wid & 1;      // warp m-offset: 64*wm
    const int wn   = wid >> 1;     // warp n-offset: 64*wn

    const int w0  = blockIdx.x * 128;
    const int h   = blockIdx.y;
    const int coh = blockIdx.z;
    const int co0 = coh * 128;

    s_bias[tid] = bias[co0 + tid];   // 128 threads -> all 128 couts

    const uint32_t sbase = (uint32_t)__cvta_generic_to_shared(dsm);

    float acc[4][8][4];
#pragma unroll
    for (int mt = 0; mt < 4; mt++)
#pragma unroll
        for (int nt = 0; nt < 8; nt++)
#pragma unroll
            for (int i = 0; i < 4; i++)
                acc[mt][nt][i] = 0.f;

    // A tile for at = kh*4 + cic2: 132 rows (pixels w0-1..w0+130),
    // 32 u32 of k per row, pitch 36 u32. 2 stages.
    auto load_A = [&](int at, int stage) {
        const int kh   = at >> 2;
        const int cic2 = at & 3;
        const uint32_t abase = sbase + A_OFF + (uint32_t)stage * ATILE_BYTES;

        const int h2 = h + kh - 1;
        const bool hok = (unsigned)h2 < (unsigned)HH;
        const int rowbase = (hok ? h2 : 0) * WW;

#pragma unroll
        for (int i = 0; i < 9; i++) {              // 1056 tasks
            const int j = tid + i * NTHREADS;
            if (j < 1056) {
                const int pix = j >> 3, q = j & 7;
                const int w2 = w0 + pix - 1;
                const bool ok = hok && ((unsigned)w2 < (unsigned)WW);
                const uint32_t* src =
                    g_x2 + ((size_t)(rowbase + (ok ? w2 : 0)) * 128 + cic2 * 32 + q * 4);
                cp_async16z(abase + (uint32_t)(pix * RPITCH + q * 4) * 4u,
                            src, ok ? 16u : 0u);
            }
        }
    };
    // B tile for chunk c (kh, cic2, kw innermost): 128 rows x 32 u32. 3 stages.
    auto load_B = [&](int c, int stage) {
        const int kh   = c / 12;
        const int r    = c % 12;
        const int cic2 = r / 3;
        const int kw   = r % 3;
        const uint32_t bbase = sbase + B_OFF + (uint32_t)stage * BTILE_BYTES;
        const uint32_t* wb =
            g_w + (((size_t)(kh * 3 + kw) * 4 + cic2) * 2 + coh) * 4096;
#pragma unroll
        for (int i = 0; i < 8; i++) {
            const int j = tid + i * NTHREADS;      // 1024 tasks
            const int n = j >> 3, q = j & 7;
            cp_async16(bbase + (uint32_t)(n * RPITCH + q * 4) * 4u, wb + j * 4);
        }
    };

    load_A(0, 0); load_B(0, 0); cp_commit();
    load_B(1, 1); cp_commit();

    // per-lane ldmatrix base offsets (bytes); pitch 144B
    const uint32_t laneA = (uint32_t)((wm * 64 + (lane & 15)) * 144 + ((lane >> 4) << 4));
    const uint32_t laneB = (uint32_t)((wn * 64 + ((lane >> 4) << 3) + (lane & 7)) * 144 +
                                      (((lane >> 3) & 1) << 4));

    for (int c = 0; c < NCHUNK; c++) {
        cp_wait1();
        __syncthreads();

        const int kw = c % 3;
        const uint32_t sA = sbase + A_OFF +
                            (uint32_t)(((c / 3) & 1) ? ATILE_BYTES : 0) +
                            (uint32_t)(kw * 144);           // kw row shift
        const uint32_t sB = sbase + B_OFF + (uint32_t)((c % 3) * BTILE_BYTES);

#pragma unroll
        for (int ks = 0; ks < 4; ks++) {
            uint32_t afrag[4][4];
#pragma unroll
            for (int mt = 0; mt < 4; mt++)
                ldsm4(afrag[mt], sA + laneA + (uint32_t)(mt * 16 * 144 + ks * 32));
            uint32_t bfrag[8][2];
#pragma unroll
            for (int np = 0; np < 4; np++) {
                uint32_t r[4];
                ldsm4(r, sB + laneB + (uint32_t)(np * 16 * 144 + ks * 32));
                bfrag[2 * np][0]     = r[0];
                bfrag[2 * np][1]     = r[1];
                bfrag[2 * np + 1][0] = r[2];
                bfrag[2 * np + 1][1] = r[3];
            }
#pragma unroll
            for (int mt = 0; mt < 4; mt++)
#pragma unroll
                for (int nt = 0; nt < 8; nt++)
                    mma_fp16(acc[mt][nt], afrag[mt], bfrag[nt]);
        }

        // no trailing __syncthreads: B 3-staged ((c+2)%3 != c%3); A prefetch
        // (only when (c+2)%3==0) targets the opposite A parity.
        const int cn = c + 2;
        if (cn < NCHUNK) {
            if (cn % 3 == 0) load_A(cn / 3, (cn / 3) & 1);
            load_B(cn, cn % 3);
        }
        cp_commit();
    }

    // ---- epilogue: bias (from smem) + streaming stores ----
    const size_t prow = (size_t)h * WW + w0;
#pragma unroll
    for (int nt = 0; nt < 8; nt++) {
        const int co = co0 + wn * 64 + nt * 8 + tig * 2;
        const float b0 = s_bias[co - co0];
        const float b1 = s_bias[co - co0 + 1];
        float* o0 = out + (size_t)co * HWSZ + prow;
        float* o1 = o0 + HWSZ;
#pragma unroll
        for (int mt = 0; mt < 4; mt++) {
            const int m = wm * 64 + mt * 16 + gid;
            stcg(o0 + m,     acc[mt][nt][0] + b0);
            stcg(o1 + m,     acc[mt][nt][1] + b1);
            stcg(o0 + m + 8, acc[mt][nt][2] + b0);
            stcg(o1 + m + 8, acc[mt][nt][3] + b1);
        }
    }
}

extern "C" void kernel_launch(void* const* d_in, const int* in_sizes, int n_in,
                              void* d_out, int out_size) {
    const float* x = (const float*)d_in[0];   // [256,512,512]
    const float* w = (const float*)d_in[1];   // [3,3,256,256]
    const float* b = (const float*)d_in[2];   // [256]
    float* out = (float*)d_out;               // [256,512,512]

    prep_x<<<(HWSZ * 4) / 256, 256>>>(x);
    prep_w<<<(9 * 4 * 2 * 128 * 32) / 256, 256>>>(w);

    cudaFuncSetAttribute(conv_mma, cudaFuncAttributeMaxDynamicSharedMemorySize, SMEM_BYTES);
    dim3 grid(4, HH, 2);   // 4 w-tiles x 512 rows x 2 cout halves
    conv_mma<<<grid, NTHREADS, SMEM_BYTES>>>(b, out);
}

// round 16
// speedup vs baseline: 1.1779x; 1.0756x over previous
#include <cuda_runtime.h>
#include <cuda_fp16.h>
#include <cstdint>

// 3x3 conv s1 p1, implicit GEMM via mma.sync m16n8k16 fp16 (f32 accum).
// R16 = R11 (best: 769.6us) with the chunk loop unrolled by 3 so kw, the B
// stage (== kw), the A parity, and all smem offsets are compile-time.
// 4 warps x 64x64 warp tiles, K-chunk 64, 2 CTAs/SM, NHWC prepass,
// ldmatrix.x4, 3-stage B / 2-stage A, A tile shared across 3 kw chunks
// via +144B row shift, no trailing barrier.

#define HH 512
#define WW 512
#define HWSZ (512*512)
#define RPITCH 36                            // u32 per row (32 used + 4 pad), 144B
#define ATILE_BYTES (132 * RPITCH * 4)       // 19008
#define BTILE_BYTES (128 * RPITCH * 4)       // 18432
#define A_OFF 0
#define B_OFF (2 * ATILE_BYTES)              // 38016
#define SMEM_BYTES (2 * ATILE_BYTES + 3 * BTILE_BYTES)   // 93312
#define NTHREADS 128
#define NCB 12                               // 12 chunk-triples = 36 chunks

// scratch (bss, not allocations)
__device__ uint32_t g_x2[HWSZ * 128];            // NHWC: [pixel][cipair] half2
__device__ uint32_t g_w[9 * 4 * 2 * 128 * 32];   // [k9][cic2][coh][n][kp32] half2

__device__ __forceinline__ uint32_t packh2(float lo, float hi) {
    uint32_t d;
    asm("cvt.rn.f16x2.f32 %0, %1, %2;" : "=r"(d) : "f"(hi), "f"(lo));
    return d;
}
__device__ __forceinline__ void cp_async16(uint32_t dst, const void* src) {
    asm volatile("cp.async.cg.shared.global [%0], [%1], 16;"
                 :: "r"(dst), "l"(src) : "memory");
}
__device__ __forceinline__ void cp_async16z(uint32_t dst, const void* src, uint32_t sz) {
    asm volatile("cp.async.cg.shared.global [%0], [%1], 16, %2;"
                 :: "r"(dst), "l"(src), "r"(sz) : "memory");
}
__device__ __forceinline__ void cp_commit() {
    asm volatile("cp.async.commit_group;" ::: "memory");
}
__device__ __forceinline__ void cp_wait1() {
    asm volatile("cp.async.wait_group 1;" ::: "memory");
}
__device__ __forceinline__ void ldsm4(uint32_t* r, uint32_t addr) {
    asm volatile("ldmatrix.sync.aligned.m8n8.x4.shared.b16 {%0,%1,%2,%3}, [%4];"
                 : "=r"(r[0]), "=r"(r[1]), "=r"(r[2]), "=r"(r[3]) : "r"(addr));
}
__device__ __forceinline__ void mma_fp16(float* c, const uint32_t* a, const uint32_t* b) {
    asm volatile(
        "mma.sync.aligned.m16n8k16.row.col.f32.f16.f16.f32 "
        "{%0,%1,%2,%3}, {%4,%5,%6,%7}, {%8,%9}, {%0,%1,%2,%3};"
        : "+f"(c[0]), "+f"(c[1]), "+f"(c[2]), "+f"(c[3])
        : "r"(a[0]), "r"(a[1]), "r"(a[2]), "r"(a[3]), "r"(b[0]), "r"(b[1]));
}

// ---------------- prepasses ----------------
__global__ void prep_x(const float* __restrict__ x) {
    const int t = blockIdx.x * 256 + threadIdx.x;   // HWSZ*4 threads
    const int p = t >> 2;
    const int j = t & 3;
#pragma unroll
    for (int i = 0; i < 8; i++) {
        const int cp0 = 4 * j + 16 * i;
        uint32_t o[4];
#pragma unroll
        for (int e = 0; e < 4; e++) {
            const int cp = cp0 + e;
            const float lo = x[(size_t)(2 * cp) * HWSZ + p];
            const float hi = x[(size_t)(2 * cp + 1) * HWSZ + p];
            o[e] = packh2(lo, hi);
        }
        *reinterpret_cast<uint4*>(g_x2 + (size_t)p * 128 + cp0) =
            make_uint4(o[0], o[1], o[2], o[3]);
    }
}
__global__ void prep_w(const float* __restrict__ w) {
    const int t = blockIdx.x * 256 + threadIdx.x;   // 294912
    const int kp   = t & 31;
    const int n    = (t >> 5) & 127;
    const int coh  = (t >> 12) & 1;
    const int cic2 = (t >> 13) & 3;
    const int k9   = t >> 15;
    const int ci = cic2 * 64 + kp * 2;
    const int co = coh * 128 + n;
    const float lo = w[((size_t)k9 * 256 + ci) * 256 + co];
    const float hi = w[((size_t)k9 * 256 + ci + 1) * 256 + co];
    g_w[((((size_t)k9 * 4 + cic2) * 2 + coh) * 128 + n) * 32 + kp] = packh2(lo, hi);
}

// ---------------- main kernel ----------------
__global__ void __launch_bounds__(NTHREADS, 2)
conv_mma(const float* __restrict__ bias, float* __restrict__ out)
{
    extern __shared__ uint32_t dsm[];

    const int tid  = threadIdx.x;
    const int wid  = tid >> 5;
    const int lane = tid & 31;
    const int gid  = lane >> 2;
    const int tig  = lane & 3;
    const int wm   = wid & 1;      // warp m-offset: 64*wm
    const int wn   = wid >> 1;     // warp n-offset: 64*wn

    const int w0  = blockIdx.x * 128;
    const int h   = blockIdx.y;
    const int coh = blockIdx.z;
    const int co0 = coh * 128;

    const uint32_t sbase = (uint32_t)__cvta_generic_to_shared(dsm);

    float acc[4][8][4];
#pragma unroll
    for (int mt = 0; mt < 4; mt++)
#pragma unroll
        for (int nt = 0; nt < 8; nt++)
#pragma unroll
            for (int i = 0; i < 4; i++)
                acc[mt][nt][i] = 0.f;

    // A tile for at = kh*4 + cic2: 132 rows (pixels w0-1..w0+130),
    // 32 u32 of k per row, pitch 36 u32. 2 stages.
    auto load_A = [&](int at, int stage) {
        const int kh   = at >> 2;
        const int cic2 = at & 3;
        const uint32_t abase = sbase + A_OFF + (uint32_t)stage * ATILE_BYTES;

        const int h2 = h + kh - 1;
        const bool hok = (unsigned)h2 < (unsigned)HH;
        const int rowbase = (hok ? h2 : 0) * WW;

#pragma unroll
        for (int i = 0; i < 9; i++) {              // 1056 tasks
            const int j = tid + i * NTHREADS;
            if (j < 1056) {
                const int pix = j >> 3, q = j & 7;
                const int w2 = w0 + pix - 1;
                const bool ok = hok && ((unsigned)w2 < (unsigned)WW);
                const uint32_t* src =
                    g_x2 + ((size_t)(rowbase + (ok ? w2 : 0)) * 128 + cic2 * 32 + q * 4);
                cp_async16z(abase + (uint32_t)(pix * RPITCH + q * 4) * 4u,
                            src, ok ? 16u : 0u);
            }
        }
    };
    // B tile for chunk (cb, kw): 128 rows x 32 u32. 3 stages, stage == kw.
    auto load_B = [&](int cb, int kw) {
        const int kh   = cb / 4;
        const int cic2 = cb & 3;
        const uint32_t bbase = sbase + B_OFF + (uint32_t)kw * BTILE_BYTES;
        const uint32_t* wb =
            g_w + (((size_t)(kh * 3 + kw) * 4 + cic2) * 2 + coh) * 4096;
#pragma unroll
        for (int i = 0; i < 8; i++) {
            const int j = tid + i * NTHREADS;      // 1024 tasks
            const int n = j >> 3, q = j & 7;
            cp_async16(bbase + (uint32_t)(n * RPITCH + q * 4) * 4u, wb + j * 4);
        }
    };

    load_A(0, 0); load_B(0, 0); cp_commit();
    load_B(0, 1); cp_commit();

    // per-lane ldmatrix base offsets (bytes); pitch 144B
    const uint32_t laneA = (uint32_t)((wm * 64 + (lane & 15)) * 144 + ((lane >> 4) << 4));
    const uint32_t laneB = (uint32_t)((wn * 64 + ((lane >> 4) << 3) + (lane & 7)) * 144 +
                                      (((lane >> 3) & 1) << 4));

    // one chunk: consume (A-stage ap with compile-time kw shift, B-stage kw),
    // then prefetch 2-ahead per the schedule below.
    auto chunk = [&](int ap, int kw, bool doLoadA, int la_at, int la_stage,
                     bool doLoadB, int lb_cb, int lb_kw) {
        cp_wait1();
        __syncthreads();

        const uint32_t sA = sbase + A_OFF + (uint32_t)(ap ? ATILE_BYTES : 0) +
                            (uint32_t)(kw * 144);
        const uint32_t sB = sbase + B_OFF + (uint32_t)(kw * BTILE_BYTES);

#pragma unroll
        for (int ks = 0; ks < 4; ks++) {
            uint32_t afrag[4][4];
#pragma unroll
            for (int mt = 0; mt < 4; mt++)
                ldsm4(afrag[mt], sA + laneA + (uint32_t)(mt * 16 * 144 + ks * 32));
            uint32_t bfrag[8][2];
#pragma unroll
            for (int np = 0; np < 4; np++) {
                uint32_t r[4];
                ldsm4(r, sB + laneB + (uint32_t)(np * 16 * 144 + ks * 32));
                bfrag[2 * np][0]     = r[0];
                bfrag[2 * np][1]     = r[1];
                bfrag[2 * np + 1][0] = r[2];
                bfrag[2 * np + 1][1] = r[3];
            }
#pragma unroll
            for (int mt = 0; mt < 4; mt++)
#pragma unroll
                for (int nt = 0; nt < 8; nt++)
                    mma_fp16(acc[mt][nt], afrag[mt], bfrag[nt]);
        }

        // no trailing __syncthreads (3-stage B / 2-stage A safety as in R11)
        if (doLoadA) load_A(la_at, la_stage);
        if (doLoadB) load_B(lb_cb, lb_kw);
        cp_commit();
    };

    // schedule for c = 3*cb + kw, prefetch target cn = c + 2:
    //  kw=0 -> cn = 3*cb+2        : B(cb, 2)
    //  kw=1 -> cn = 3*(cb+1)      : A(cb+1), B(cb+1, 0)
    //  kw=2 -> cn = 3*(cb+1)+1    : B(cb+1, 1)
#pragma unroll 1
    for (int cb = 0; cb < NCB; cb++) {
        const int ap = cb & 1;
        const bool more = (cb + 1) < NCB;
        chunk(ap, 0, false, 0, 0, true, cb, 2);
        chunk(ap, 1, more, cb + 1, (cb + 1) & 1, more, cb + 1, 0);
        chunk(ap, 2, false, 0, 0, more, cb + 1, 1);
    }

    // ---- epilogue: bias + store ----
    const size_t prow = (size_t)h * WW + w0;
#pragma unroll
    for (int nt = 0; nt < 8; nt++) {
        const int co = co0 + wn * 64 + nt * 8 + tig * 2;
        const float b0 = __ldg(bias + co);
        const float b1 = __ldg(bias + co + 1);
        float* o0 = out + (size_t)co * HWSZ + prow;
        float* o1 = o0 + HWSZ;
#pragma unroll
        for (int mt = 0; mt < 4; mt++) {
            const int m = wm * 64 + mt * 16 + gid;
            o0[m]     = acc[mt][nt][0] + b0;
            o1[m]     = acc[mt][nt][1] + b1;
            o0[m + 8] = acc[mt][nt][2] + b0;
            o1[m + 8] = acc[mt][nt][3] + b1;
        }
    }
}

extern "C" void kernel_launch(void* const* d_in, const int* in_sizes, int n_in,
                              void* d_out, int out_size) {
    const float* x = (const float*)d_in[0];   // [256,512,512]
    const float* w = (const float*)d_in[1];   // [3,3,256,256]
    const float* b = (const float*)d_in[2];   // [256]
    float* out = (float*)d_out;               // [256,512,512]

    prep_x<<<(HWSZ * 4) / 256, 256>>>(x);
    prep_w<<<(9 * 4 * 2 * 128 * 32) / 256, 256>>>(w);

    cudaFuncSetAttribute(conv_mma, cudaFuncAttributeMaxDynamicSharedMemorySize, SMEM_BYTES);
    dim3 grid(4, HH, 2);   // 4 w-tiles x 512 rows x 2 cout halves
    conv_mma<<<grid, NTHREADS, SMEM_BYTES>>>(b, out);
}

// round 17
// speedup vs baseline: 1.2067x; 1.0245x over previous
#include <cuda_runtime.h>
#include <cuda_fp16.h>
#include <cstdint>

// 3x3 conv s1 p1, implicit GEMM via mma.sync m16n8k16 fp16 (f32 accum).
// R17 = R16 (best: 719.7us) with the triple loop unrolled by 2 so the A
// stage parity (ap) is also compile-time -> every LDSM address is
// lane-reg + immediate. Schedule, stages, and safety identical to R16.
// 4 warps x 64x64 warp tiles, K-chunk 64, 2 CTAs/SM, NHWC prepass,
// ldmatrix.x4, 3-stage B (stage==kw) / 2-stage A, A tile shared across
// 3 kw chunks via +144B row shift, no trailing barrier.

#define HH 512
#define WW 512
#define HWSZ (512*512)
#define RPITCH 36                            // u32 per row (32 used + 4 pad), 144B
#define ATILE_BYTES (132 * RPITCH * 4)       // 19008
#define BTILE_BYTES (128 * RPITCH * 4)       // 18432
#define A_OFF 0
#define B_OFF (2 * ATILE_BYTES)              // 38016
#define SMEM_BYTES (2 * ATILE_BYTES + 3 * BTILE_BYTES)   // 93312
#define NTHREADS 128
#define NCB 12                               // 12 chunk-triples = 36 chunks

// scratch (bss, not allocations)
__device__ uint32_t g_x2[HWSZ * 128];            // NHWC: [pixel][cipair] half2
__device__ uint32_t g_w[9 * 4 * 2 * 128 * 32];   // [k9][cic2][coh][n][kp32] half2

__device__ __forceinline__ uint32_t packh2(float lo, float hi) {
    uint32_t d;
    asm("cvt.rn.f16x2.f32 %0, %1, %2;" : "=r"(d) : "f"(hi), "f"(lo));
    return d;
}
__device__ __forceinline__ void cp_async16(uint32_t dst, const void* src) {
    asm volatile("cp.async.cg.shared.global [%0], [%1], 16;"
                 :: "r"(dst), "l"(src) : "memory");
}
__device__ __forceinline__ void cp_async16z(uint32_t dst, const void* src, uint32_t sz) {
    asm volatile("cp.async.cg.shared.global [%0], [%1], 16, %2;"
                 :: "r"(dst), "l"(src), "r"(sz) : "memory");
}
__device__ __forceinline__ void cp_commit() {
    asm volatile("cp.async.commit_group;" ::: "memory");
}
__device__ __forceinline__ void cp_wait1() {
    asm volatile("cp.async.wait_group 1;" ::: "memory");
}
__device__ __forceinline__ void ldsm4(uint32_t* r, uint32_t addr) {
    asm volatile("ldmatrix.sync.aligned.m8n8.x4.shared.b16 {%0,%1,%2,%3}, [%4];"
                 : "=r"(r[0]), "=r"(r[1]), "=r"(r[2]), "=r"(r[3]) : "r"(addr));
}
__device__ __forceinline__ void mma_fp16(float* c, const uint32_t* a, const uint32_t* b) {
    asm volatile(
        "mma.sync.aligned.m16n8k16.row.col.f32.f16.f16.f32 "
        "{%0,%1,%2,%3}, {%4,%5,%6,%7}, {%8,%9}, {%0,%1,%2,%3};"
        : "+f"(c[0]), "+f"(c[1]), "+f"(c[2]), "+f"(c[3])
        : "r"(a[0]), "r"(a[1]), "r"(a[2]), "r"(a[3]), "r"(b[0]), "r"(b[1]));
}

// ---------------- prepasses ----------------
__global__ void prep_x(const float* __restrict__ x) {
    const int t = blockIdx.x * 256 + threadIdx.x;   // HWSZ*4 threads
    const int p = t >> 2;
    const int j = t & 3;
#pragma unroll
    for (int i = 0; i < 8; i++) {
        const int cp0 = 4 * j + 16 * i;
        uint32_t o[4];
#pragma unroll
        for (int e = 0; e < 4; e++) {
            const int cp = cp0 + e;
            const float lo = x[(size_t)(2 * cp) * HWSZ + p];
            const float hi = x[(size_t)(2 * cp + 1) * HWSZ + p];
            o[e] = packh2(lo, hi);
        }
        *reinterpret_cast<uint4*>(g_x2 + (size_t)p * 128 + cp0) =
            make_uint4(o[0], o[1], o[2], o[3]);
    }
}
__global__ void prep_w(const float* __restrict__ w) {
    const int t = blockIdx.x * 256 + threadIdx.x;   // 294912
    const int kp   = t & 31;
    const int n    = (t >> 5) & 127;
    const int coh  = (t >> 12) & 1;
    const int cic2 = (t >> 13) & 3;
    const int k9   = t >> 15;
    const int ci = cic2 * 64 + kp * 2;
    const int co = coh * 128 + n;
    const float lo = w[((size_t)k9 * 256 + ci) * 256 + co];
    const float hi = w[((size_t)k9 * 256 + ci + 1) * 256 + co];
    g_w[((((size_t)k9 * 4 + cic2) * 2 + coh) * 128 + n) * 32 + kp] = packh2(lo, hi);
}

// ---------------- main kernel ----------------
__global__ void __launch_bounds__(NTHREADS, 2)
conv_mma(const float* __restrict__ bias, float* __restrict__ out)
{
    extern __shared__ uint32_t dsm[];

    const int tid  = threadIdx.x;
    const int wid  = tid >> 5;
    const int lane = tid & 31;
    const int gid  = lane >> 2;
    const int tig  = lane & 3;
    const int wm   = wid & 1;      // warp m-offset: 64*wm
    const int wn   = wid >> 1;     // warp n-offset: 64*wn

    const int w0  = blockIdx.x * 128;
    const int h   = blockIdx.y;
    const int coh = blockIdx.z;
    const int co0 = coh * 128;

    const uint32_t sbase = (uint32_t)__cvta_generic_to_shared(dsm);

    float acc[4][8][4];
#pragma unroll
    for (int mt = 0; mt < 4; mt++)
#pragma unroll
        for (int nt = 0; nt < 8; nt++)
#pragma unroll
            for (int i = 0; i < 4; i++)
                acc[mt][nt][i] = 0.f;

    // A tile for at = kh*4 + cic2: 132 rows (pixels w0-1..w0+130),
    // 32 u32 of k per row, pitch 36 u32. 2 stages.
    auto load_A = [&](int at, int stage) {
        const int kh   = at >> 2;
        const int cic2 = at & 3;
        const uint32_t abase = sbase + A_OFF + (uint32_t)stage * ATILE_BYTES;

        const int h2 = h + kh - 1;
        const bool hok = (unsigned)h2 < (unsigned)HH;
        const int rowbase = (hok ? h2 : 0) * WW;

#pragma unroll
        for (int i = 0; i < 9; i++) {              // 1056 tasks
            const int j = tid + i * NTHREADS;
            if (j < 1056) {
                const int pix = j >> 3, q = j & 7;
                const int w2 = w0 + pix - 1;
                const bool ok = hok && ((unsigned)w2 < (unsigned)WW);
                const uint32_t* src =
                    g_x2 + ((size_t)(rowbase + (ok ? w2 : 0)) * 128 + cic2 * 32 + q * 4);
                cp_async16z(abase + (uint32_t)(pix * RPITCH + q * 4) * 4u,
                            src, ok ? 16u : 0u);
            }
        }
    };
    // B tile for chunk (cb, kw): 128 rows x 32 u32. 3 stages, stage == kw.
    auto load_B = [&](int cb, int kw) {
        const int kh   = cb / 4;
        const int cic2 = cb & 3;
        const uint32_t bbase = sbase + B_OFF + (uint32_t)kw * BTILE_BYTES;
        const uint32_t* wb =
            g_w + (((size_t)(kh * 3 + kw) * 4 + cic2) * 2 + coh) * 4096;
#pragma unroll
        for (int i = 0; i < 8; i++) {
            const int j = tid + i * NTHREADS;      // 1024 tasks
            const int n = j >> 3, q = j & 7;
            cp_async16(bbase + (uint32_t)(n * RPITCH + q * 4) * 4u, wb + j * 4);
        }
    };

    load_A(0, 0); load_B(0, 0); cp_commit();
    load_B(0, 1); cp_commit();

    // per-lane ldmatrix base offsets (bytes); pitch 144B
    const uint32_t laneA = (uint32_t)((wm * 64 + (lane & 15)) * 144 + ((lane >> 4) << 4));
    const uint32_t laneB = (uint32_t)((wn * 64 + ((lane >> 4) << 3) + (lane & 7)) * 144 +
                                      (((lane >> 3) & 1) << 4));

    // one chunk with compile-time (ap, kw); prefetch 2-ahead per schedule.
    auto chunk = [&](int ap, int kw, bool doLoadA, int la_at, int la_stage,
                     bool doLoadB, int lb_cb, int lb_kw) {
        cp_wait1();
        __syncthreads();

        const uint32_t sA = sbase + A_OFF + (uint32_t)(ap ? ATILE_BYTES : 0) +
                            (uint32_t)(kw * 144);
        const uint32_t sB = sbase + B_OFF + (uint32_t)(kw * BTILE_BYTES);

#pragma unroll
        for (int ks = 0; ks < 4; ks++) {
            uint32_t afrag[4][4];
#pragma unroll
            for (int mt = 0; mt < 4; mt++)
                ldsm4(afrag[mt], sA + laneA + (uint32_t)(mt * 16 * 144 + ks * 32));
            uint32_t bfrag[8][2];
#pragma unroll
            for (int np = 0; np < 4; np++) {
                uint32_t r[4];
                ldsm4(r, sB + laneB + (uint32_t)(np * 16 * 144 + ks * 32));
                bfrag[2 * np][0]     = r[0];
                bfrag[2 * np][1]     = r[1];
                bfrag[2 * np + 1][0] = r[2];
                bfrag[2 * np + 1][1] = r[3];
            }
#pragma unroll
            for (int mt = 0; mt < 4; mt++)
#pragma unroll
                for (int nt = 0; nt < 8; nt++)
                    mma_fp16(acc[mt][nt], afrag[mt], bfrag[nt]);
        }

        // no trailing __syncthreads (3-stage B / 2-stage A safety as in R16)
        if (doLoadA) load_A(la_at, la_stage);
        if (doLoadB) load_B(lb_cb, lb_kw);
        cp_commit();
    };

    // same schedule as R16 (c = 3*cb + kw, prefetch cn = c + 2), but the
    // cb loop is unrolled by 2 so ap is a compile-time constant in each body.
#pragma unroll 1
    for (int cb2 = 0; cb2 < NCB; cb2 += 2) {
        {   // even triple: ap = 0
            const int cb = cb2;
            chunk(0, 0, false, 0, 0, true, cb, 2);
            chunk(0, 1, true, cb + 1, 1, true, cb + 1, 0);
            chunk(0, 2, false, 0, 0, true, cb + 1, 1);
        }
        {   // odd triple: ap = 1
            const int cb = cb2 + 1;
            const bool more = (cb + 1) < NCB;
            chunk(1, 0, false, 0, 0, true, cb, 2);
            chunk(1, 1, more, cb + 1, 0, more, cb + 1, 0);
            chunk(1, 2, false, 0, 0, more, cb + 1, 1);
        }
    }

    // ---- epilogue: bias + store ----
    const size_t prow = (size_t)h * WW + w0;
#pragma unroll
    for (int nt = 0; nt < 8; nt++) {
        const int co = co0 + wn * 64 + nt * 8 + tig * 2;
        const float b0 = __ldg(bias + co);
        const float b1 = __ldg(bias + co + 1);
        float* o0 = out + (size_t)co * HWSZ + prow;
        float* o1 = o0 + HWSZ;
#pragma unroll
        for (int mt = 0; mt < 4; mt++) {
            const int m = wm * 64 + mt * 16 + gid;
            o0[m]     = acc[mt][nt][0] + b0;
            o1[m]     = acc[mt][nt][1] + b1;
            o0[m + 8] = acc[mt][nt][2] + b0;
            o1[m + 8] = acc[mt][nt][3] + b1;
        }
    }
}

extern "C" void kernel_launch(void* const* d_in, const int* in_sizes, int n_in,
                              void* d_out, int out_size) {
    const float* x = (const float*)d_in[0];   // [256,512,512]
    const float* w = (const float*)d_in[1];   // [3,3,256,256]
    const float* b = (const float*)d_in[2];   // [256]
    float* out = (float*)d_out;               // [256,512,512]

    prep_x<<<(HWSZ * 4) / 256, 256>>>(x);
    prep_w<<<(9 * 4 * 2 * 128 * 32) / 256, 256>>>(w);

    cudaFuncSetAttribute(conv_mma, cudaFuncAttributeMaxDynamicSharedMemorySize, SMEM_BYTES);
    dim3 grid(4, HH, 2);   // 4 w-tiles x 512 rows x 2 cout halves
    conv_mma<<<grid, NTHREADS, SMEM_BYTES>>>(b, out);
}